// round 11
// baseline (speedup 1.0000x reference)
#include <cuda_runtime.h>
#include <cuda_bf16.h>

// EdgeMLP via split-bf16 warp-level MMA (mma.sync m16n8k16, bf16->f32).
// out = silu( silu( LN( [src|edge] @ W1 + b1 ) ) @ W2 + b2 ), fp32 I/O.
// x = xh + xl (truncated hi + bf16 residual); x*w ~= xh*wh + xh*wl + xl*wh.
//
// v3: two independent 256-thread pipelines per CTA (64-row tiles each),
// named barriers only -> group A's staging/LN (alu/mem) overlaps group B's
// MMA phases (tensor) via scheduler anti-phase. Weights shared in SMEM.

typedef unsigned int u32;
typedef unsigned short u16;
typedef unsigned long long u64;

static constexpr int THREADS = 512;
static constexpr int GBR = 64;               // rows per group-tile
static constexpr int NODE = 128, EDGED = 64, OUTD = 128;

// ---- smem byte offsets ----
static constexpr int OFF_W1AH = 0;           // W1 k<128:  [n=128][k=128] bf16 hi
static constexpr int OFF_W1AL = 32768;
static constexpr int OFF_W1BH = 65536;       // W1 k>=128: [128][64]
static constexpr int OFF_W1BL = 81920;
static constexpr int OFF_W2H  = 98304;       // [128][128]
static constexpr int OFF_W2L  = 131072;
static constexpr int OFF_BUF  = 163840;      // 2 x 32KB group regions (X/H hi+lo,
                                             //   raw cp.async target, LN partials)
static constexpr int OFF_B1 = 229376, OFF_B2 = 229888;
static constexpr int OFF_G  = 230400, OFF_BT = 230912;
static constexpr int SMEM_BYTES = 231424;    // <= 232448

__device__ __forceinline__ u32 smem_u32(const void* p) {
    u32 a;
    asm("{ .reg .u64 t; cvta.to.shared.u64 t, %1; cvt.u32.u64 %0, t; }"
        : "=r"(a) : "l"(p));
    return a;
}
__device__ __forceinline__ float silu_f(float y) {
    return __fdividef(y, 1.0f + __expf(-y));
}
// hi16(a) low half, hi16(b) high half (truncation split)
__device__ __forceinline__ u32 pack_hi2(float a, float b) {
    return __byte_perm(__float_as_uint(a), __float_as_uint(b), 0x7632);
}
// bf16(residual(a)) low, bf16(residual(b)) high
__device__ __forceinline__ u32 pack_lo2(float a, float b) {
    const float ra = a - __uint_as_float(__float_as_uint(a) & 0xFFFF0000u);
    const float rb = b - __uint_as_float(__float_as_uint(b) & 0xFFFF0000u);
    u32 r;
    asm("cvt.rn.bf16x2.f32 %0, %1, %2;" : "=r"(r) : "f"(rb), "f"(ra));
    return r;
}
__device__ __forceinline__ void cp16(u32 dst, const void* gsrc) {
    asm volatile("cp.async.ca.shared.global [%0], [%1], 16;"
                 :: "r"(dst), "l"(gsrc) : "memory");
}
#define CP_COMMIT() asm volatile("cp.async.commit_group;" ::: "memory")
#define CP_WAIT0()  asm volatile("cp.async.wait_group 0;" ::: "memory")
#define NBAR(id)    asm volatile("bar.sync %0, 256;" :: "r"(id) : "memory")

// 16B chunk address of (row, k) in a [rows][NC*8 k] bf16 tile, chunk-swizzled.
template <int NC>
__device__ __forceinline__ u32 fr_addr(u32 base, int row, int k) {
    return base + (((row * NC) + ((k >> 3) ^ (row & 7))) << 4);
}

#define LDSM4(R0, R1, R2, R3, A)                                          \
    asm volatile("ldmatrix.sync.aligned.m8n8.x4.shared.b16 {%0,%1,%2,%3}, [%4];" \
                 : "=r"(R0), "=r"(R1), "=r"(R2), "=r"(R3) : "r"(A))

__device__ __forceinline__ void mma_bf16(float* c, u32 a0, u32 a1, u32 a2, u32 a3,
                                         u32 b0, u32 b1) {
    asm volatile(
        "mma.sync.aligned.m16n8k16.row.col.f32.bf16.bf16.f32 "
        "{%0,%1,%2,%3}, {%4,%5,%6,%7}, {%8,%9}, {%0,%1,%2,%3};"
        : "+f"(c[0]), "+f"(c[1]), "+f"(c[2]), "+f"(c[3])
        : "r"(a0), "r"(a1), "r"(a2), "r"(a3), "r"(b0), "r"(b1));
}

// One k16 step: acc[2 mtiles][4 ntiles][4] += A(32xk16) x B(k16x32), 3 terms.
// A rows are group-local (0..63 via wm in {0,1}).
template <int NCA, int NCB>
__device__ __forceinline__ void k_step(u32 aH, u32 aL, u32 bH, u32 bL,
                                       int wm, int wn, int k0,
                                       float acc[2][4][4], int lane) {
    const int la7 = lane & 7;
    const int arow = wm * 32 + la7 + (((lane >> 3) & 1) << 3);
    const int ak   = k0 + ((lane >> 4) << 3);
    const int brow = wn * 32 + la7 + ((lane >> 4) << 3);
    const int bk   = k0 + (((lane >> 3) & 1) << 3);

    u32 ah[8], al[8], bh[8], bl[8];
    LDSM4(ah[0], ah[1], ah[2], ah[3], fr_addr<NCA>(aH, arow, ak));
    LDSM4(ah[4], ah[5], ah[6], ah[7], fr_addr<NCA>(aH, arow + 16, ak));
    LDSM4(al[0], al[1], al[2], al[3], fr_addr<NCA>(aL, arow, ak));
    LDSM4(al[4], al[5], al[6], al[7], fr_addr<NCA>(aL, arow + 16, ak));
    LDSM4(bh[0], bh[1], bh[2], bh[3], fr_addr<NCB>(bH, brow, bk));
    LDSM4(bh[4], bh[5], bh[6], bh[7], fr_addr<NCB>(bH, brow + 16, bk));
    LDSM4(bl[0], bl[1], bl[2], bl[3], fr_addr<NCB>(bL, brow, bk));
    LDSM4(bl[4], bl[5], bl[6], bl[7], fr_addr<NCB>(bL, brow + 16, bk));

#pragma unroll
    for (int mt = 0; mt < 2; mt++) {
        const u32* Ah = ah + 4 * mt;
        const u32* Al = al + 4 * mt;
#pragma unroll
        for (int nt = 0; nt < 4; nt++) {
            const u32 B0h = bh[2 * nt], B1h = bh[2 * nt + 1];
            const u32 B0l = bl[2 * nt], B1l = bl[2 * nt + 1];
            float* C = acc[mt][nt];
            mma_bf16(C, Ah[0], Ah[1], Ah[2], Ah[3], B0h, B1h);
            mma_bf16(C, Ah[0], Ah[1], Ah[2], Ah[3], B0l, B1l);
            mma_bf16(C, Al[0], Al[1], Al[2], Al[3], B0h, B1h);
        }
    }
}

__global__ void __launch_bounds__(THREADS, 1)
edge_mlp_mma(const float* __restrict__ src, const float* __restrict__ edg,
             const float* __restrict__ W1,  const float* __restrict__ b1,
             const float* __restrict__ gam, const float* __restrict__ bet,
             const float* __restrict__ W2,  const float* __restrict__ b2,
             float* __restrict__ out, int E, int nt64) {
    extern __shared__ char smc[];
    const u32 sb = smem_u32(smc);
    const int tid  = threadIdx.x;
    const int warp = tid >> 5, lane = tid & 31;
    const int grp  = warp >> 3;            // 0 or 1: independent pipeline
    const int gtid = tid & 255;
    const int gwarp = warp & 7;
    const int wm = gwarp >> 2, wn = gwarp & 3;   // warp: rows wm*32, cols wn*32
    const int g = lane >> 2, tig = lane & 3;
    const int barid = 1 + grp;
    const u32 BUFG = OFF_BUF + grp * 32768;      // group's 32KB region
    const u32 bufH = sb + BUFG, bufL = sb + BUFG + 16384;

    // ---- prefetch first group-tile's raw src (32KB) ----
    {
        const int t0 = blockIdx.x * 2 + grp;
        if (t0 < nt64) {
            const int rowbase = t0 * GBR;
            const float4* s4 = (const float4*)(src + (size_t)rowbase * NODE);
#pragma unroll
            for (int j = 0; j < 8; j++) {
                const int i = gtid + j * 256;
                const int r = i >> 5;
                if (rowbase + r < E) cp16(sb + BUFG + (i << 4), s4 + i);
                else *(float4*)(smc + BUFG + (i << 4)) = make_float4(0.f, 0.f, 0.f, 0.f);
            }
        }
        CP_COMMIT();
    }

    // ---- one-time: split weights hi/lo into [n][k] swizzled tiles ----
    for (int i = tid; i < 192 * 128; i += THREADS) {
        const int k = i >> 7, n = i & 127;
        const float w = W1[i];
        const u16 h = (u16)(__float_as_uint(w) >> 16);
        const u16 l = (u16)(pack_lo2(w, 0.f) & 0xFFFFu);
        if (k < 128) {
            const u32 byte = ((n * 16 + ((k >> 3) ^ (n & 7))) << 4) + ((k & 7) << 1);
            *(u16*)(smc + OFF_W1AH + byte) = h;
            *(u16*)(smc + OFF_W1AL + byte) = l;
        } else {
            const int k2 = k - 128;
            const u32 byte = ((n * 8 + ((k2 >> 3) ^ (n & 7))) << 4) + ((k2 & 7) << 1);
            *(u16*)(smc + OFF_W1BH + byte) = h;
            *(u16*)(smc + OFF_W1BL + byte) = l;
        }
    }
    for (int i = tid; i < 128 * 128; i += THREADS) {
        const int k = i >> 7, n = i & 127;
        const float w = W2[i];
        const u32 byte = ((n * 16 + ((k >> 3) ^ (n & 7))) << 4) + ((k & 7) << 1);
        *(u16*)(smc + OFF_W2H + byte) = (u16)(__float_as_uint(w) >> 16);
        *(u16*)(smc + OFF_W2L + byte) = (u16)(pack_lo2(w, 0.f) & 0xFFFFu);
    }
    if (tid < 128) {
        ((float*)(smc + OFF_B1))[tid] = b1[tid];
        ((float*)(smc + OFF_B2))[tid] = b2[tid];
        ((float*)(smc + OFF_G))[tid]  = gam[tid];
        ((float*)(smc + OFF_BT))[tid] = bet[tid];
    }
    const float* b1f = (const float*)(smc + OFF_B1);
    const float* b2f = (const float*)(smc + OFF_B2);
    const float* gf  = (const float*)(smc + OFF_G);
    const float* btf = (const float*)(smc + OFF_BT);

    __syncthreads();   // last CTA-wide sync: weights ready for both groups

    for (int tile = blockIdx.x * 2 + grp; tile < nt64; tile += gridDim.x * 2) {
        const int rowbase = tile * GBR;
        const bool full = (rowbase + GBR <= E);

        // ---- convert prefetched raw src -> bf16 hi/lo in place ----
        CP_WAIT0();
        NBAR(barid);   // all group threads' cp.async data landed
        {
            float4 xa[8];
#pragma unroll
            for (int j = 0; j < 8; j++)
                xa[j] = *(const float4*)(smc + BUFG + ((gtid + j * 256) << 4));
            NBAR(barid);   // raw reads complete before overwriting
#pragma unroll
            for (int j = 0; j < 8; j++) {
                const int i = gtid + j * 256;
                const int r = i >> 5, c4 = i & 31;
                const float4 v = xa[j];
                const u32 byte = ((r * 16 + ((c4 >> 1) ^ (r & 7))) << 4) + ((c4 & 1) << 3);
                *(u64*)(smc + BUFG + byte) =
                    (u64)pack_hi2(v.x, v.y) | ((u64)pack_hi2(v.z, v.w) << 32);
                *(u64*)(smc + BUFG + 16384 + byte) =
                    (u64)pack_lo2(v.x, v.y) | ((u64)pack_lo2(v.z, v.w) << 32);
            }
        }
        NBAR(barid);

        // ---- GEMM1 part A: src x W1[k<128] ----
        float acc[2][4][4];
#pragma unroll
        for (int mt = 0; mt < 2; mt++)
#pragma unroll
            for (int nt = 0; nt < 4; nt++)
#pragma unroll
                for (int q = 0; q < 4; q++) acc[mt][nt][q] = 0.f;
#pragma unroll 2
        for (int ks = 0; ks < 8; ks++)
            k_step<16, 16>(bufH, bufL, sb + OFF_W1AH, sb + OFF_W1AL,
                           wm, wn, ks * 16, acc, lane);
        NBAR(barid);   // src reads done

        // ---- stage edge chunk (64x64, direct LDG) ----
        {
            const float4* s4 = (const float4*)(edg + (size_t)rowbase * EDGED);
#pragma unroll
            for (int j = 0; j < 4; j++) {
                const int i = gtid + j * 256;
                const int r = i >> 4, c4 = i & 15;
                float4 v = make_float4(0.f, 0.f, 0.f, 0.f);
                if (full || rowbase + r < E) v = s4[i];
                const u32 byte = ((r * 8 + ((c4 >> 1) ^ (r & 7))) << 4) + ((c4 & 1) << 3);
                *(u64*)(smc + BUFG + byte) =
                    (u64)pack_hi2(v.x, v.y) | ((u64)pack_hi2(v.z, v.w) << 32);
                *(u64*)(smc + BUFG + 16384 + byte) =
                    (u64)pack_lo2(v.x, v.y) | ((u64)pack_lo2(v.z, v.w) << 32);
            }
        }
        NBAR(barid);

        // ---- GEMM1 part B: edge x W1[k>=128] ----
#pragma unroll 2
        for (int ks = 0; ks < 4; ks++)
            k_step<8, 8>(bufH, bufL, sb + OFF_W1BH, sb + OFF_W1BL,
                         wm, wn, ks * 16, acc, lane);
        NBAR(barid);   // edge reads done; region free for partials

        // ---- bias + LN partial sums (thread covers 4 rows x 8 cols) ----
        float s1[4] = {0.f, 0.f, 0.f, 0.f}, s2[4] = {0.f, 0.f, 0.f, 0.f};
#pragma unroll
        for (int mt = 0; mt < 2; mt++)
#pragma unroll
            for (int nt = 0; nt < 4; nt++) {
                const int c0 = wn * 32 + nt * 8 + 2 * tig;
                float* C = acc[mt][nt];
                C[0] += b1f[c0]; C[1] += b1f[c0 + 1];
                C[2] += b1f[c0]; C[3] += b1f[c0 + 1];
                s1[2 * mt]     += C[0] + C[1];
                s2[2 * mt]     += C[0] * C[0] + C[1] * C[1];
                s1[2 * mt + 1] += C[2] + C[3];
                s2[2 * mt + 1] += C[2] * C[2] + C[3] * C[3];
            }
#pragma unroll
        for (int j = 0; j < 4; j++) {
            s1[j] += __shfl_xor_sync(0xffffffffu, s1[j], 1);
            s1[j] += __shfl_xor_sync(0xffffffffu, s1[j], 2);
            s2[j] += __shfl_xor_sync(0xffffffffu, s2[j], 1);
            s2[j] += __shfl_xor_sync(0xffffffffu, s2[j], 2);
        }
        float2* part = (float2*)(smc + BUFG);   // 64 rows x 4 = 2KB, aliases H region
        if (tig == 0) {
#pragma unroll
            for (int j = 0; j < 4; j++) {
                const int row = wm * 32 + ((j >> 1) << 4) + ((j & 1) << 3) + g;
                part[row * 4 + wn] = make_float2(s1[j], s2[j]);
            }
        }
        NBAR(barid);

        float mus[4], rss[4];
#pragma unroll
        for (int j = 0; j < 4; j++) {
            const int row = wm * 32 + ((j >> 1) << 4) + ((j & 1) << 3) + g;
            const float2 q0 = part[row * 4 + 0], q1 = part[row * 4 + 1];
            const float2 q2 = part[row * 4 + 2], q3 = part[row * 4 + 3];
            const float m1 = (q0.x + q1.x + q2.x + q3.x) * (1.0f / 128.0f);
            const float m2 = (q0.y + q1.y + q2.y + q3.y) * (1.0f / 128.0f);
            mus[j] = m1;
            rss[j] = rsqrtf(m2 - m1 * m1 + 1e-5f);
        }
        NBAR(barid);   // partials consumed; region writable as H

        // ---- LN apply + SiLU + split -> H (bf16 hi/lo, swizzled) ----
#pragma unroll
        for (int mt = 0; mt < 2; mt++)
#pragma unroll
            for (int nt = 0; nt < 4; nt++) {
                const int c0 = wn * 32 + nt * 8 + 2 * tig;
                float* C = acc[mt][nt];
#pragma unroll
                for (int h = 0; h < 2; h++) {
                    const int j = 2 * mt + h;
                    const int row = wm * 32 + mt * 16 + h * 8 + g;
                    const float y0 = silu_f((C[2 * h + 0] - mus[j]) * rss[j] * gf[c0]     + btf[c0]);
                    const float y1 = silu_f((C[2 * h + 1] - mus[j]) * rss[j] * gf[c0 + 1] + btf[c0 + 1]);
                    const u32 byte = ((row * 16 + ((c0 >> 3) ^ (row & 7))) << 4)
                                   + ((c0 & 7) << 1);
                    *(u32*)(smc + BUFG + byte)         = pack_hi2(y0, y1);
                    *(u32*)(smc + BUFG + 16384 + byte) = pack_lo2(y0, y1);
                }
            }
        NBAR(barid);

        // ---- GEMM2: H x W2 ----
#pragma unroll
        for (int mt = 0; mt < 2; mt++)
#pragma unroll
            for (int nt = 0; nt < 4; nt++)
#pragma unroll
                for (int q = 0; q < 4; q++) acc[mt][nt][q] = 0.f;
#pragma unroll 2
        for (int ks = 0; ks < 8; ks++)
            k_step<16, 16>(bufH, bufL, sb + OFF_W2H, sb + OFF_W2L,
                           wm, wn, ks * 16, acc, lane);
        NBAR(barid);   // all group warps done reading H

        // ---- prefetch next group-tile's raw src (overlaps epilogue) ----
        {
            const int ntile = tile + gridDim.x * 2;
            if (ntile < nt64) {
                const int nrb = ntile * GBR;
                const float4* s4 = (const float4*)(src + (size_t)nrb * NODE);
#pragma unroll
                for (int j = 0; j < 8; j++) {
                    const int i = gtid + j * 256;
                    const int r = i >> 5;
                    if (nrb + r < E) cp16(sb + BUFG + (i << 4), s4 + i);
                    else *(float4*)(smc + BUFG + (i << 4)) =
                             make_float4(0.f, 0.f, 0.f, 0.f);
                }
            }
            CP_COMMIT();
        }

        // ---- epilogue: bias + SiLU + store ----
#pragma unroll
        for (int mt = 0; mt < 2; mt++)
#pragma unroll
            for (int nt = 0; nt < 4; nt++) {
                const int c0 = wn * 32 + nt * 8 + 2 * tig;
                float* C = acc[mt][nt];
#pragma unroll
                for (int h = 0; h < 2; h++) {
                    const int row = rowbase + wm * 32 + mt * 16 + h * 8 + g;
                    if (row < E) {
                        float2 o;
                        o.x = silu_f(C[2 * h + 0] + b2f[c0]);
                        o.y = silu_f(C[2 * h + 1] + b2f[c0 + 1]);
                        *(float2*)(out + (size_t)row * OUTD + c0) = o;
                    }
                }
            }
    }
}

extern "C" void kernel_launch(void* const* d_in, const int* in_sizes, int n_in,
                              void* d_out, int out_size) {
    const float* src = (const float*)d_in[0];
    const float* edg = (const float*)d_in[1];
    const float* W1  = (const float*)d_in[2];
    const float* b1  = (const float*)d_in[3];
    const float* gam = (const float*)d_in[4];
    const float* bet = (const float*)d_in[5];
    const float* W2  = (const float*)d_in[6];
    const float* b2  = (const float*)d_in[7];
    float* out = (float*)d_out;

    const int E = in_sizes[0] / NODE;
    const int nt64 = (E + GBR - 1) / GBR;

    cudaFuncSetAttribute(edge_mlp_mma,
                         cudaFuncAttributeMaxDynamicSharedMemorySize, SMEM_BYTES);

    int nsm = 148;
    if (cudaDeviceGetAttribute(&nsm, cudaDevAttrMultiProcessorCount, 0) != cudaSuccess
        || nsm <= 0)
        nsm = 148;
    const int maxg = (nt64 + 1) / 2;
    const int grid = nsm < maxg ? nsm : maxg;

    edge_mlp_mma<<<grid, THREADS, SMEM_BYTES>>>(src, edg, W1, b1, gam, bet,
                                                W2, b2, out, E, nt64);
}

// round 12
// speedup vs baseline: 1.5364x; 1.5364x over previous
#include <cuda_runtime.h>
#include <cuda_fp16.h>

// EdgeMLP via 2-term split-fp16 warp-level MMA (mma.sync m16n8k16, f16->f32).
// out = silu( silu( LN( [src|edge] @ W1 + b1 ) ) @ W2 + b2 ), fp32 I/O.
// x ~ xh (fp16);  w = wh + wl (fp16 each);  x*w ~= xh*wh + xh*wl.
// Dropped xl*w ~ 2^-12 relative -> rel_err ~1.5e-4 << 1e-3 tolerance.
// v4: reverted to single-pipeline 128-row tiles (v2 structure), fp16 2-term
// halves A-side staging and cuts MMA count by 1/3; edge chunk now also
// cp.async-prefetched (overlaps GEMM1-A).

typedef unsigned int u32;
typedef unsigned short u16;
typedef unsigned long long u64;

static constexpr int THREADS = 512;
static constexpr int BR = 128, NODE = 128, EDGED = 64, OUTD = 128;

// ---- smem byte offsets ----
static constexpr int OFF_W1AH = 0;        // W1 k<128:  [n=128][k=128] fp16 hi
static constexpr int OFF_W1AL = 32768;    //            fp16 lo
static constexpr int OFF_W1BH = 65536;    // W1 k>=128: [128][64]
static constexpr int OFF_W1BL = 81920;
static constexpr int OFF_W2H  = 98304;    // [128][128]
static constexpr int OFF_W2L  = 131072;
static constexpr int OFF_BUF  = 163840;   // 64KB: raw src stage / X,H fp16 (first
                                          // 32KB) + edge raw/fp16 (second 32KB)
static constexpr int OFF_B1 = 229376, OFF_B2 = 229888;
static constexpr int OFF_G  = 230400, OFF_BT = 230912;
static constexpr int SMEM_BYTES = 231424; // <= 232448

__device__ __forceinline__ u32 smem_u32(const void* p) {
    u32 a;
    asm("{ .reg .u64 t; cvta.to.shared.u64 t, %1; cvt.u32.u64 %0, t; }"
        : "=r"(a) : "l"(p));
    return a;
}
__device__ __forceinline__ float silu_f(float y) {
    return __fdividef(y, 1.0f + __expf(-y));
}
// fp16(a) in low half, fp16(b) in high half
__device__ __forceinline__ u32 pack_f16x2(float a, float b) {
    u32 r;
    asm("cvt.rn.f16x2.f32 %0, %1, %2;" : "=r"(r) : "f"(b), "f"(a));
    return r;
}
__device__ __forceinline__ void cp16(u32 dst, const void* gsrc) {
    asm volatile("cp.async.ca.shared.global [%0], [%1], 16;"
                 :: "r"(dst), "l"(gsrc) : "memory");
}
#define CP_COMMIT() asm volatile("cp.async.commit_group;" ::: "memory")
#define CP_WAIT0()  asm volatile("cp.async.wait_group 0;" ::: "memory")

// 16B chunk address of (row, k) in a [rows][NC*8 k] fp16 tile, chunk-swizzled
// (chunk ^ (row & 7)) -> ldmatrix phases conflict-free.
template <int NC>
__device__ __forceinline__ u32 fr_addr(u32 base, int row, int k) {
    return base + (((row * NC) + ((k >> 3) ^ (row & 7))) << 4);
}

#define LDSM4(R0, R1, R2, R3, A)                                          \
    asm volatile("ldmatrix.sync.aligned.m8n8.x4.shared.b16 {%0,%1,%2,%3}, [%4];" \
                 : "=r"(R0), "=r"(R1), "=r"(R2), "=r"(R3) : "r"(A))

__device__ __forceinline__ void mma_f16(float* c, u32 a0, u32 a1, u32 a2, u32 a3,
                                        u32 b0, u32 b1) {
    asm volatile(
        "mma.sync.aligned.m16n8k16.row.col.f32.f16.f16.f32 "
        "{%0,%1,%2,%3}, {%4,%5,%6,%7}, {%8,%9}, {%0,%1,%2,%3};"
        : "+f"(c[0]), "+f"(c[1]), "+f"(c[2]), "+f"(c[3])
        : "r"(a0), "r"(a1), "r"(a2), "r"(a3), "r"(b0), "r"(b1));
}

// One k16 step: acc[2 mtiles][4 ntiles][4] += A(32xk16) x (Bh+Bl)(k16x32).
template <int NCA, int NCB>
__device__ __forceinline__ void k_step(u32 aP, u32 bH, u32 bL,
                                       int wm, int wn, int k0,
                                       float acc[2][4][4], int lane) {
    const int la7 = lane & 7;
    const int arow = wm * 32 + la7 + (((lane >> 3) & 1) << 3);
    const int ak   = k0 + ((lane >> 4) << 3);
    const int brow = wn * 32 + la7 + ((lane >> 4) << 3);
    const int bk   = k0 + (((lane >> 3) & 1) << 3);

    u32 ah[8], bh[8], bl[8];
    LDSM4(ah[0], ah[1], ah[2], ah[3], fr_addr<NCA>(aP, arow, ak));
    LDSM4(ah[4], ah[5], ah[6], ah[7], fr_addr<NCA>(aP, arow + 16, ak));
    LDSM4(bh[0], bh[1], bh[2], bh[3], fr_addr<NCB>(bH, brow, bk));
    LDSM4(bh[4], bh[5], bh[6], bh[7], fr_addr<NCB>(bH, brow + 16, bk));
    LDSM4(bl[0], bl[1], bl[2], bl[3], fr_addr<NCB>(bL, brow, bk));
    LDSM4(bl[4], bl[5], bl[6], bl[7], fr_addr<NCB>(bL, brow + 16, bk));

#pragma unroll
    for (int mt = 0; mt < 2; mt++) {
        const u32* A = ah + 4 * mt;
#pragma unroll
        for (int nt = 0; nt < 4; nt++) {
            float* C = acc[mt][nt];
            mma_f16(C, A[0], A[1], A[2], A[3], bh[2 * nt], bh[2 * nt + 1]);
            mma_f16(C, A[0], A[1], A[2], A[3], bl[2 * nt], bl[2 * nt + 1]);
        }
    }
}

__global__ void __launch_bounds__(THREADS, 1)
edge_mlp_mma(const float* __restrict__ src, const float* __restrict__ edg,
             const float* __restrict__ W1,  const float* __restrict__ b1,
             const float* __restrict__ gam, const float* __restrict__ bet,
             const float* __restrict__ W2,  const float* __restrict__ b2,
             float* __restrict__ out, int E, int ntiles) {
    extern __shared__ char smc[];
    const u32 sb = smem_u32(smc);
    const int tid = threadIdx.x;
    const int warp = tid >> 5, lane = tid & 31;
    const int wm = warp >> 2, wn = warp & 3;   // warp: rows wm*32, cols wn*32
    const int g = lane >> 2, tig = lane & 3;
    const u32 bufX = sb + OFF_BUF;             // X/H fp16 [128][128] (32KB)
    const u32 bufE = sb + OFF_BUF + 32768;     // edge raw / fp16 [128][64]

    // ---- prefetch first tile's raw src (64KB into whole BUF) ----
    {
        const int rowbase = blockIdx.x * BR;
        const float4* s4 = (const float4*)(src + (size_t)rowbase * NODE);
#pragma unroll
        for (int j = 0; j < 8; j++) {
            const int i = tid + j * THREADS;
            const int r = i >> 5;
            if (rowbase + r < E) cp16(sb + OFF_BUF + (i << 4), s4 + i);
            else *(float4*)(smc + OFF_BUF + (i << 4)) = make_float4(0.f, 0.f, 0.f, 0.f);
        }
        CP_COMMIT();
    }

    // ---- one-time: split weights into fp16 hi/lo [n][k] swizzled tiles ----
    for (int i = tid; i < 192 * 128; i += THREADS) {
        const int k = i >> 7, n = i & 127;
        const float w = W1[i];
        const __half hh = __float2half_rn(w);
        const __half hl = __float2half_rn(w - __half2float(hh));
        if (k < 128) {
            const u32 byte = ((n * 16 + ((k >> 3) ^ (n & 7))) << 4) + ((k & 7) << 1);
            *(u16*)(smc + OFF_W1AH + byte) = __half_as_ushort(hh);
            *(u16*)(smc + OFF_W1AL + byte) = __half_as_ushort(hl);
        } else {
            const int k2 = k - 128;
            const u32 byte = ((n * 8 + ((k2 >> 3) ^ (n & 7))) << 4) + ((k2 & 7) << 1);
            *(u16*)(smc + OFF_W1BH + byte) = __half_as_ushort(hh);
            *(u16*)(smc + OFF_W1BL + byte) = __half_as_ushort(hl);
        }
    }
    for (int i = tid; i < 128 * 128; i += THREADS) {
        const int k = i >> 7, n = i & 127;
        const float w = W2[i];
        const __half hh = __float2half_rn(w);
        const __half hl = __float2half_rn(w - __half2float(hh));
        const u32 byte = ((n * 16 + ((k >> 3) ^ (n & 7))) << 4) + ((k & 7) << 1);
        *(u16*)(smc + OFF_W2H + byte) = __half_as_ushort(hh);
        *(u16*)(smc + OFF_W2L + byte) = __half_as_ushort(hl);
    }
    if (tid < 128) {
        ((float*)(smc + OFF_B1))[tid] = b1[tid];
        ((float*)(smc + OFF_B2))[tid] = b2[tid];
        ((float*)(smc + OFF_G))[tid]  = gam[tid];
        ((float*)(smc + OFF_BT))[tid] = bet[tid];
    }
    const float* b1f = (const float*)(smc + OFF_B1);
    const float* b2f = (const float*)(smc + OFF_B2);
    const float* gf  = (const float*)(smc + OFF_G);
    const float* btf = (const float*)(smc + OFF_BT);

    for (int tile = blockIdx.x; tile < ntiles; tile += gridDim.x) {
        const int rowbase = tile * BR;
        const bool full = (rowbase + BR <= E);

        // ---- convert raw src (64KB in BUF) -> X fp16 (first 32KB) ----
        CP_WAIT0();
        __syncthreads();   // cp data landed everywhere; weights ready (iter 0)
        {
            float4 xa[8];
#pragma unroll
            for (int j = 0; j < 8; j++)
                xa[j] = *(const float4*)(smc + OFF_BUF + ((tid + j * THREADS) << 4));
            __syncthreads();   // all raw reads done before overwriting
#pragma unroll
            for (int j = 0; j < 8; j++) {
                const int i = tid + j * THREADS;
                const int r = i >> 5, c4 = i & 31;
                const float4 v = xa[j];
                const u32 byte = ((r * 16 + ((c4 >> 1) ^ (r & 7))) << 4) + ((c4 & 1) << 3);
                *(u64*)(smc + OFF_BUF + byte) =
                    (u64)pack_f16x2(v.x, v.y) | ((u64)pack_f16x2(v.z, v.w) << 32);
            }
            // prefetch edge raw (32KB) into second half — overlaps GEMM1-A
            const float4* e4 = (const float4*)(edg + (size_t)rowbase * EDGED);
#pragma unroll
            for (int j = 0; j < 4; j++) {
                const int i = tid + j * THREADS;
                const int r = i >> 4;
                if (full || rowbase + r < E) cp16(bufE + (i << 4), e4 + i);
                else *(float4*)(smc + OFF_BUF + 32768 + (i << 4)) =
                         make_float4(0.f, 0.f, 0.f, 0.f);
            }
            CP_COMMIT();
        }
        __syncthreads();

        // ---- GEMM1 part A: src x W1[k<128] ----
        float acc[2][4][4];
#pragma unroll
        for (int mt = 0; mt < 2; mt++)
#pragma unroll
            for (int nt = 0; nt < 4; nt++)
#pragma unroll
                for (int q = 0; q < 4; q++) acc[mt][nt][q] = 0.f;
#pragma unroll 2
        for (int ks = 0; ks < 8; ks++)
            k_step<16, 16>(bufX, sb + OFF_W1AH, sb + OFF_W1AL,
                           wm, wn, ks * 16, acc, lane);

        // ---- convert edge raw -> fp16 in place (second half of BUF) ----
        CP_WAIT0();
        {
            float4 ea[4];
#pragma unroll
            for (int j = 0; j < 4; j++)
                ea[j] = *(const float4*)(smc + OFF_BUF + 32768 + ((tid + j * THREADS) << 4));
            __syncthreads();   // all edge raw reads done (also closes GEMM1-A reads)
#pragma unroll
            for (int j = 0; j < 4; j++) {
                const int i = tid + j * THREADS;
                const int r = i >> 4, c4 = i & 15;
                const float4 v = ea[j];
                const u32 byte = ((r * 8 + ((c4 >> 1) ^ (r & 7))) << 4) + ((c4 & 1) << 3);
                *(u64*)(smc + OFF_BUF + 32768 + byte) =
                    (u64)pack_f16x2(v.x, v.y) | ((u64)pack_f16x2(v.z, v.w) << 32);
            }
        }
        __syncthreads();

        // ---- GEMM1 part B: edge x W1[k>=128] ----
#pragma unroll 2
        for (int ks = 0; ks < 4; ks++)
            k_step<8, 8>(bufE, sb + OFF_W1BH, sb + OFF_W1BL,
                         wm, wn, ks * 16, acc, lane);
        __syncthreads();   // edge reads done; X region free for partials

        // ---- bias + LN partial sums (thread covers 4 rows x 8 cols) ----
        float s1[4] = {0.f, 0.f, 0.f, 0.f}, s2[4] = {0.f, 0.f, 0.f, 0.f};
#pragma unroll
        for (int mt = 0; mt < 2; mt++)
#pragma unroll
            for (int nt = 0; nt < 4; nt++) {
                const int c0 = wn * 32 + nt * 8 + 2 * tig;
                float* C = acc[mt][nt];
                C[0] += b1f[c0]; C[1] += b1f[c0 + 1];
                C[2] += b1f[c0]; C[3] += b1f[c0 + 1];
                s1[2 * mt]     += C[0] + C[1];
                s2[2 * mt]     += C[0] * C[0] + C[1] * C[1];
                s1[2 * mt + 1] += C[2] + C[3];
                s2[2 * mt + 1] += C[2] * C[2] + C[3] * C[3];
            }
#pragma unroll
        for (int j = 0; j < 4; j++) {
            s1[j] += __shfl_xor_sync(0xffffffffu, s1[j], 1);
            s1[j] += __shfl_xor_sync(0xffffffffu, s1[j], 2);
            s2[j] += __shfl_xor_sync(0xffffffffu, s2[j], 1);
            s2[j] += __shfl_xor_sync(0xffffffffu, s2[j], 2);
        }
        float2* part = (float2*)(smc + OFF_BUF);   // 128 rows x 4 = 4KB
        if (tig == 0) {
#pragma unroll
            for (int j = 0; j < 4; j++) {
                const int row = wm * 32 + ((j >> 1) << 4) + ((j & 1) << 3) + g;
                part[row * 4 + wn] = make_float2(s1[j], s2[j]);
            }
        }
        __syncthreads();

        float mus[4], rss[4];
#pragma unroll
        for (int j = 0; j < 4; j++) {
            const int row = wm * 32 + ((j >> 1) << 4) + ((j & 1) << 3) + g;
            const float2 q0 = part[row * 4 + 0], q1 = part[row * 4 + 1];
            const float2 q2 = part[row * 4 + 2], q3 = part[row * 4 + 3];
            const float m1 = (q0.x + q1.x + q2.x + q3.x) * (1.0f / 128.0f);
            const float m2 = (q0.y + q1.y + q2.y + q3.y) * (1.0f / 128.0f);
            mus[j] = m1;
            rss[j] = rsqrtf(m2 - m1 * m1 + 1e-5f);
        }
        __syncthreads();   // partials consumed; X region writable as H

        // ---- LN apply + SiLU -> H fp16 (swizzled, first 32KB) ----
#pragma unroll
        for (int mt = 0; mt < 2; mt++)
#pragma unroll
            for (int nt = 0; nt < 4; nt++) {
                const int c0 = wn * 32 + nt * 8 + 2 * tig;
                float* C = acc[mt][nt];
#pragma unroll
                for (int h = 0; h < 2; h++) {
                    const int j = 2 * mt + h;
                    const int row = wm * 32 + mt * 16 + h * 8 + g;
                    const float y0 = silu_f((C[2 * h + 0] - mus[j]) * rss[j] * gf[c0]     + btf[c0]);
                    const float y1 = silu_f((C[2 * h + 1] - mus[j]) * rss[j] * gf[c0 + 1] + btf[c0 + 1]);
                    const u32 byte = ((row * 16 + ((c0 >> 3) ^ (row & 7))) << 4)
                                   + ((c0 & 7) << 1);
                    *(u32*)(smc + OFF_BUF + byte) = pack_f16x2(y0, y1);
                }
            }
        __syncthreads();

        // ---- GEMM2: H x W2 ----
#pragma unroll
        for (int mt = 0; mt < 2; mt++)
#pragma unroll
            for (int nt = 0; nt < 4; nt++)
#pragma unroll
                for (int q = 0; q < 4; q++) acc[mt][nt][q] = 0.f;
#pragma unroll 2
        for (int ks = 0; ks < 8; ks++)
            k_step<16, 16>(bufX, sb + OFF_W2H, sb + OFF_W2L,
                           wm, wn, ks * 16, acc, lane);
        __syncthreads();   // all warps done reading H

        // ---- prefetch next tile's raw src (overlaps epilogue) ----
        {
            const int ntile = tile + gridDim.x;
            if (ntile < ntiles) {
                const int nrb = ntile * BR;
                const float4* s4 = (const float4*)(src + (size_t)nrb * NODE);
#pragma unroll
                for (int j = 0; j < 8; j++) {
                    const int i = tid + j * THREADS;
                    const int r = i >> 5;
                    if (nrb + r < E) cp16(sb + OFF_BUF + (i << 4), s4 + i);
                    else *(float4*)(smc + OFF_BUF + (i << 4)) =
                             make_float4(0.f, 0.f, 0.f, 0.f);
                }
            }
            CP_COMMIT();
        }

        // ---- epilogue: bias + SiLU + store ----
#pragma unroll
        for (int mt = 0; mt < 2; mt++)
#pragma unroll
            for (int nt = 0; nt < 4; nt++) {
                const int c0 = wn * 32 + nt * 8 + 2 * tig;
                float* C = acc[mt][nt];
#pragma unroll
                for (int h = 0; h < 2; h++) {
                    const int row = rowbase + wm * 32 + mt * 16 + h * 8 + g;
                    if (row < E) {
                        float2 o;
                        o.x = silu_f(C[2 * h + 0] + b2f[c0]);
                        o.y = silu_f(C[2 * h + 1] + b2f[c0 + 1]);
                        *(float2*)(out + (size_t)row * OUTD + c0) = o;
                    }
                }
            }
    }
}

extern "C" void kernel_launch(void* const* d_in, const int* in_sizes, int n_in,
                              void* d_out, int out_size) {
    const float* src = (const float*)d_in[0];
    const float* edg = (const float*)d_in[1];
    const float* W1  = (const float*)d_in[2];
    const float* b1  = (const float*)d_in[3];
    const float* gam = (const float*)d_in[4];
    const float* bet = (const float*)d_in[5];
    const float* W2  = (const float*)d_in[6];
    const float* b2  = (const float*)d_in[7];
    float* out = (float*)d_out;

    const int E = in_sizes[0] / NODE;
    const int ntiles = (E + BR - 1) / BR;

    cudaFuncSetAttribute(edge_mlp_mma,
                         cudaFuncAttributeMaxDynamicSharedMemorySize, SMEM_BYTES);

    int nsm = 148;
    if (cudaDeviceGetAttribute(&nsm, cudaDevAttrMultiProcessorCount, 0) != cudaSuccess
        || nsm <= 0)
        nsm = 148;
    const int grid = nsm < ntiles ? nsm : ntiles;

    edge_mlp_mma<<<grid, THREADS, SMEM_BYTES>>>(src, edg, W1, b1, gam, bet,
                                                W2, b2, out, E, ntiles);
}

// round 14
// speedup vs baseline: 1.7363x; 1.1301x over previous
#include <cuda_runtime.h>
#include <cuda_fp16.h>

// EdgeMLP via 2-term split-fp16 warp-level MMA (mma.sync m16n8k16, f16->f32).
// out = silu( silu( LN( [src|edge] @ W1 + b1 ) ) @ W2 + b2 ), fp32 I/O.
// x ~ fp16(x);  w = wh + wl (fp16 each);  x*w ~= xh*wh + xh*wl.
// v5: tanh.approx-based SiLU (1 MUFU instead of 2; MUFU was ~15% of cycles),
// next-tile src prefetch split into two 32KB halves issued earlier
// (post-GEMM1B and post-GEMM2) so the DRAM drain is fully covered.

typedef unsigned int u32;
typedef unsigned short u16;
typedef unsigned long long u64;

static constexpr int THREADS = 512;
static constexpr int BR = 128, NODE = 128, EDGED = 64, OUTD = 128;

// ---- smem byte offsets ----
static constexpr int OFF_W1AH = 0;        // W1 k<128:  [n=128][k=128] fp16 hi
static constexpr int OFF_W1AL = 32768;    //            fp16 lo
static constexpr int OFF_W1BH = 65536;    // W1 k>=128: [128][64]
static constexpr int OFF_W1BL = 81920;
static constexpr int OFF_W2H  = 98304;    // [128][128]
static constexpr int OFF_W2L  = 131072;
static constexpr int OFF_BUF  = 163840;   // 64KB: X/H fp16 (first 32KB) +
                                          // edge raw/fp16 (second 32KB).
                                          // Raw next-src is split: rows 0-63
                                          // in second half, rows 64-127 first.
static constexpr int OFF_B1 = 229376, OFF_B2 = 229888;
static constexpr int OFF_G  = 230400, OFF_BT = 230912;
static constexpr int SMEM_BYTES = 231424; // <= 232448

__device__ __forceinline__ u32 smem_u32(const void* p) {
    u32 a;
    asm("{ .reg .u64 t; cvta.to.shared.u64 t, %1; cvt.u32.u64 %0, t; }"
        : "=r"(a) : "l"(p));
    return a;
}
// silu(y) = y*sigmoid(y) = t + t*tanh(t), t = y/2  (single MUFU op)
__device__ __forceinline__ float silu_f(float y) {
    const float t = 0.5f * y;
    float s;
    asm("tanh.approx.f32 %0, %1;" : "=f"(s) : "f"(t));
    return fmaf(t, s, t);
}
// fp16(a) in low half, fp16(b) in high half
__device__ __forceinline__ u32 pack_f16x2(float a, float b) {
    u32 r;
    asm("cvt.rn.f16x2.f32 %0, %1, %2;" : "=r"(r) : "f"(b), "f"(a));
    return r;
}
__device__ __forceinline__ void cp16(u32 dst, const void* gsrc) {
    asm volatile("cp.async.ca.shared.global [%0], [%1], 16;"
                 :: "r"(dst), "l"(gsrc) : "memory");
}
#define CP_COMMIT() asm volatile("cp.async.commit_group;" ::: "memory")
#define CP_WAIT0()  asm volatile("cp.async.wait_group 0;" ::: "memory")

// 16B chunk address of (row, k) in a [rows][NC*8 k] fp16 tile, chunk-swizzled
// (chunk ^ (row & 7)) -> ldmatrix phases conflict-free.
template <int NC>
__device__ __forceinline__ u32 fr_addr(u32 base, int row, int k) {
    return base + (((row * NC) + ((k >> 3) ^ (row & 7))) << 4);
}

#define LDSM4(R0, R1, R2, R3, A)                                          \
    asm volatile("ldmatrix.sync.aligned.m8n8.x4.shared.b16 {%0,%1,%2,%3}, [%4];" \
                 : "=r"(R0), "=r"(R1), "=r"(R2), "=r"(R3) : "r"(A))

__device__ __forceinline__ void mma_f16(float* c, u32 a0, u32 a1, u32 a2, u32 a3,
                                        u32 b0, u32 b1) {
    asm volatile(
        "mma.sync.aligned.m16n8k16.row.col.f32.f16.f16.f32 "
        "{%0,%1,%2,%3}, {%4,%5,%6,%7}, {%8,%9}, {%0,%1,%2,%3};"
        : "+f"(c[0]), "+f"(c[1]), "+f"(c[2]), "+f"(c[3])
        : "r"(a0), "r"(a1), "r"(a2), "r"(a3), "r"(b0), "r"(b1));
}

// One k16 step: acc[2 mtiles][4 ntiles][4] += A(32xk16) x (Bh+Bl)(k16x32).
template <int NCA, int NCB>
__device__ __forceinline__ void k_step(u32 aP, u32 bH, u32 bL,
                                       int wm, int wn, int k0,
                                       float acc[2][4][4], int lane) {
    const int la7 = lane & 7;
    const int arow = wm * 32 + la7 + (((lane >> 3) & 1) << 3);
    const int ak   = k0 + ((lane >> 4) << 3);
    const int brow = wn * 32 + la7 + ((lane >> 4) << 3);
    const int bk   = k0 + (((lane >> 3) & 1) << 3);

    u32 ah[8], bh[8], bl[8];
    LDSM4(ah[0], ah[1], ah[2], ah[3], fr_addr<NCA>(aP, arow, ak));
    LDSM4(ah[4], ah[5], ah[6], ah[7], fr_addr<NCA>(aP, arow + 16, ak));
    LDSM4(bh[0], bh[1], bh[2], bh[3], fr_addr<NCB>(bH, brow, bk));
    LDSM4(bh[4], bh[5], bh[6], bh[7], fr_addr<NCB>(bH, brow + 16, bk));
    LDSM4(bl[0], bl[1], bl[2], bl[3], fr_addr<NCB>(bL, brow, bk));
    LDSM4(bl[4], bl[5], bl[6], bl[7], fr_addr<NCB>(bL, brow + 16, bk));

#pragma unroll
    for (int mt = 0; mt < 2; mt++) {
        const u32* A = ah + 4 * mt;
#pragma unroll
        for (int nt = 0; nt < 4; nt++) {
            float* C = acc[mt][nt];
            mma_f16(C, A[0], A[1], A[2], A[3], bh[2 * nt], bh[2 * nt + 1]);
            mma_f16(C, A[0], A[1], A[2], A[3], bl[2 * nt], bl[2 * nt + 1]);
        }
    }
}

__global__ void __launch_bounds__(THREADS, 1)
edge_mlp_mma(const float* __restrict__ src, const float* __restrict__ edg,
             const float* __restrict__ W1,  const float* __restrict__ b1,
             const float* __restrict__ gam, const float* __restrict__ bet,
             const float* __restrict__ W2,  const float* __restrict__ b2,
             float* __restrict__ out, int E, int ntiles) {
    extern __shared__ char smc[];
    const u32 sb = smem_u32(smc);
    const int tid = threadIdx.x;
    const int warp = tid >> 5, lane = tid & 31;
    const int wm = warp >> 2, wn = warp & 3;   // warp: rows wm*32, cols wn*32
    const int g = lane >> 2, tig = lane & 3;
    const u32 bufX = sb + OFF_BUF;             // X/H fp16 [128][128] (32KB)
    const u32 bufE = sb + OFF_BUF + 32768;     // edge raw/fp16; src raw rows 0-63

    // raw-src split layout: chunk i (i>>5 = row): rows 0-63 -> bufE + i*16,
    // rows 64-127 -> bufX + (i-2048)*16.
    // lower-half prefetch (rows 0-63, 32KB into bufE)
    auto pf_lo = [&](int rowbase) {
        const float4* s4 = (const float4*)(src + (size_t)rowbase * NODE);
#pragma unroll
        for (int j = 0; j < 4; j++) {
            const int i = tid + j * THREADS;        // [0,2048)
            const int r = i >> 5;
            if (rowbase + r < E) cp16(bufE + (i << 4), s4 + i);
            else *(float4*)(smc + OFF_BUF + 32768 + (i << 4)) =
                     make_float4(0.f, 0.f, 0.f, 0.f);
        }
    };
    // upper-half prefetch (rows 64-127, 32KB into bufX)
    auto pf_hi = [&](int rowbase) {
        const float4* s4 = (const float4*)(src + (size_t)rowbase * NODE);
#pragma unroll
        for (int j = 0; j < 4; j++) {
            const int i = 2048 + tid + j * THREADS; // [2048,4096)
            const int r = i >> 5;
            if (rowbase + r < E) cp16(bufX + ((i - 2048) << 4), s4 + i);
            else *(float4*)(smc + OFF_BUF + ((i - 2048) << 4)) =
                     make_float4(0.f, 0.f, 0.f, 0.f);
        }
    };

    // ---- prefetch first tile's raw src ----
    {
        const int rowbase = blockIdx.x * BR;
        pf_lo(rowbase);
        pf_hi(rowbase);
        CP_COMMIT();
    }

    // ---- one-time: split weights into fp16 hi/lo [n][k] swizzled tiles ----
    for (int i = tid; i < 192 * 128; i += THREADS) {
        const int k = i >> 7, n = i & 127;
        const float w = W1[i];
        const __half hh = __float2half_rn(w);
        const __half hl = __float2half_rn(w - __half2float(hh));
        if (k < 128) {
            const u32 byte = ((n * 16 + ((k >> 3) ^ (n & 7))) << 4) + ((k & 7) << 1);
            *(u16*)(smc + OFF_W1AH + byte) = __half_as_ushort(hh);
            *(u16*)(smc + OFF_W1AL + byte) = __half_as_ushort(hl);
        } else {
            const int k2 = k - 128;
            const u32 byte = ((n * 8 + ((k2 >> 3) ^ (n & 7))) << 4) + ((k2 & 7) << 1);
            *(u16*)(smc + OFF_W1BH + byte) = __half_as_ushort(hh);
            *(u16*)(smc + OFF_W1BL + byte) = __half_as_ushort(hl);
        }
    }
    for (int i = tid; i < 128 * 128; i += THREADS) {
        const int k = i >> 7, n = i & 127;
        const float w = W2[i];
        const __half hh = __float2half_rn(w);
        const __half hl = __float2half_rn(w - __half2float(hh));
        const u32 byte = ((n * 16 + ((k >> 3) ^ (n & 7))) << 4) + ((k & 7) << 1);
        *(u16*)(smc + OFF_W2H + byte) = __half_as_ushort(hh);
        *(u16*)(smc + OFF_W2L + byte) = __half_as_ushort(hl);
    }
    if (tid < 128) {
        ((float*)(smc + OFF_B1))[tid] = b1[tid];
        ((float*)(smc + OFF_B2))[tid] = b2[tid];
        ((float*)(smc + OFF_G))[tid]  = gam[tid];
        ((float*)(smc + OFF_BT))[tid] = bet[tid];
    }
    const float* b1f = (const float*)(smc + OFF_B1);
    const float* b2f = (const float*)(smc + OFF_B2);
    const float* gf  = (const float*)(smc + OFF_G);
    const float* btf = (const float*)(smc + OFF_BT);

    for (int tile = blockIdx.x; tile < ntiles; tile += gridDim.x) {
        const int rowbase = tile * BR;
        const bool full = (rowbase + BR <= E);
        const int ntile = tile + gridDim.x;

        // ---- convert raw src (split layout) -> X fp16 (first 32KB) ----
        CP_WAIT0();
        __syncthreads();   // cp data landed everywhere; weights ready (iter 0)
        {
            float4 xa[8];
#pragma unroll
            for (int j = 0; j < 8; j++) {
                const int i = tid + j * THREADS;
                const int off = (i < 2048) ? (32768 + (i << 4)) : ((i - 2048) << 4);
                xa[j] = *(const float4*)(smc + OFF_BUF + off);
            }
            __syncthreads();   // all raw reads done before overwriting
#pragma unroll
            for (int j = 0; j < 8; j++) {
                const int i = tid + j * THREADS;
                const int r = i >> 5, c4 = i & 31;
                const float4 v = xa[j];
                const u32 byte = ((r * 16 + ((c4 >> 1) ^ (r & 7))) << 4) + ((c4 & 1) << 3);
                *(u64*)(smc + OFF_BUF + byte) =
                    (u64)pack_f16x2(v.x, v.y) | ((u64)pack_f16x2(v.z, v.w) << 32);
            }
            // prefetch edge raw (32KB) into bufE — overlaps GEMM1-A
            const float4* e4 = (const float4*)(edg + (size_t)rowbase * EDGED);
#pragma unroll
            for (int j = 0; j < 4; j++) {
                const int i = tid + j * THREADS;
                const int r = i >> 4;
                if (full || rowbase + r < E) cp16(bufE + (i << 4), e4 + i);
                else *(float4*)(smc + OFF_BUF + 32768 + (i << 4)) =
                         make_float4(0.f, 0.f, 0.f, 0.f);
            }
            CP_COMMIT();
        }
        __syncthreads();

        // ---- GEMM1 part A: src x W1[k<128] ----
        float acc[2][4][4];
#pragma unroll
        for (int mt = 0; mt < 2; mt++)
#pragma unroll
            for (int nt = 0; nt < 4; nt++)
#pragma unroll
                for (int q = 0; q < 4; q++) acc[mt][nt][q] = 0.f;
#pragma unroll 2
        for (int ks = 0; ks < 8; ks++)
            k_step<16, 16>(bufX, sb + OFF_W1AH, sb + OFF_W1AL,
                           wm, wn, ks * 16, acc, lane);

        // ---- convert edge raw -> fp16 in place (bufE) ----
        CP_WAIT0();
        {
            float4 ea[4];
#pragma unroll
            for (int j = 0; j < 4; j++)
                ea[j] = *(const float4*)(smc + OFF_BUF + 32768 + ((tid + j * THREADS) << 4));
            __syncthreads();   // edge raw reads done (also closes GEMM1-A reads)
#pragma unroll
            for (int j = 0; j < 4; j++) {
                const int i = tid + j * THREADS;
                const int r = i >> 4, c4 = i & 15;
                const float4 v = ea[j];
                const u32 byte = ((r * 8 + ((c4 >> 1) ^ (r & 7))) << 4) + ((c4 & 1) << 3);
                *(u64*)(smc + OFF_BUF + 32768 + byte) =
                    (u64)pack_f16x2(v.x, v.y) | ((u64)pack_f16x2(v.z, v.w) << 32);
            }
        }
        __syncthreads();

        // ---- GEMM1 part B: edge x W1[k>=128] ----
#pragma unroll 2
        for (int ks = 0; ks < 4; ks++)
            k_step<8, 8>(bufE, sb + OFF_W1BH, sb + OFF_W1BL,
                         wm, wn, ks * 16, acc, lane);
        __syncthreads();   // edge reads done; bufE free

        // ---- prefetch next tile's src rows 0-63 into bufE (long slack) ----
        if (ntile < ntiles) pf_lo(ntile * BR);
        CP_COMMIT();

        // ---- bias + LN partial sums (thread covers 4 rows x 8 cols) ----
        float s1[4] = {0.f, 0.f, 0.f, 0.f}, s2[4] = {0.f, 0.f, 0.f, 0.f};
#pragma unroll
        for (int mt = 0; mt < 2; mt++)
#pragma unroll
            for (int nt = 0; nt < 4; nt++) {
                const int c0 = wn * 32 + nt * 8 + 2 * tig;
                float* C = acc[mt][nt];
                C[0] += b1f[c0]; C[1] += b1f[c0 + 1];
                C[2] += b1f[c0]; C[3] += b1f[c0 + 1];
                s1[2 * mt]     += C[0] + C[1];
                s2[2 * mt]     += C[0] * C[0] + C[1] * C[1];
                s1[2 * mt + 1] += C[2] + C[3];
                s2[2 * mt + 1] += C[2] * C[2] + C[3] * C[3];
            }
#pragma unroll
        for (int j = 0; j < 4; j++) {
            s1[j] += __shfl_xor_sync(0xffffffffu, s1[j], 1);
            s1[j] += __shfl_xor_sync(0xffffffffu, s1[j], 2);
            s2[j] += __shfl_xor_sync(0xffffffffu, s2[j], 1);
            s2[j] += __shfl_xor_sync(0xffffffffu, s2[j], 2);
        }
        float2* part = (float2*)(smc + OFF_BUF);   // first 4KB of X region
        if (tig == 0) {
#pragma unroll
            for (int j = 0; j < 4; j++) {
                const int row = wm * 32 + ((j >> 1) << 4) + ((j & 1) << 3) + g;
                part[row * 4 + wn] = make_float2(s1[j], s2[j]);
            }
        }
        __syncthreads();

        float mus[4], rss[4];
#pragma unroll
        for (int j = 0; j < 4; j++) {
            const int row = wm * 32 + ((j >> 1) << 4) + ((j & 1) << 3) + g;
            const float2 q0 = part[row * 4 + 0], q1 = part[row * 4 + 1];
            const float2 q2 = part[row * 4 + 2], q3 = part[row * 4 + 3];
            const float m1 = (q0.x + q1.x + q2.x + q3.x) * (1.0f / 128.0f);
            const float m2 = (q0.y + q1.y + q2.y + q3.y) * (1.0f / 128.0f);
            mus[j] = m1;
            rss[j] = rsqrtf(m2 - m1 * m1 + 1e-5f);
        }
        __syncthreads();   // partials consumed; X region writable as H

        // ---- LN apply + SiLU -> H fp16 (swizzled, first 32KB) ----
#pragma unroll
        for (int mt = 0; mt < 2; mt++)
#pragma unroll
            for (int nt = 0; nt < 4; nt++) {
                const int c0 = wn * 32 + nt * 8 + 2 * tig;
                float* C = acc[mt][nt];
#pragma unroll
                for (int h = 0; h < 2; h++) {
                    const int j = 2 * mt + h;
                    const int row = wm * 32 + mt * 16 + h * 8 + g;
                    const float y0 = silu_f((C[2 * h + 0] - mus[j]) * rss[j] * gf[c0]     + btf[c0]);
                    const float y1 = silu_f((C[2 * h + 1] - mus[j]) * rss[j] * gf[c0 + 1] + btf[c0 + 1]);
                    const u32 byte = ((row * 16 + ((c0 >> 3) ^ (row & 7))) << 4)
                                   + ((c0 & 7) << 1);
                    *(u32*)(smc + OFF_BUF + byte) = pack_f16x2(y0, y1);
                }
            }
        __syncthreads();

        // ---- GEMM2: H x W2 ----
#pragma unroll
        for (int mt = 0; mt < 2; mt++)
#pragma unroll
            for (int nt = 0; nt < 4; nt++)
#pragma unroll
                for (int q = 0; q < 4; q++) acc[mt][nt][q] = 0.f;
#pragma unroll 2
        for (int ks = 0; ks < 8; ks++)
            k_step<16, 16>(bufX, sb + OFF_W2H, sb + OFF_W2L,
                           wm, wn, ks * 16, acc, lane);
        __syncthreads();   // all warps done reading H; bufX free

        // ---- prefetch next tile's src rows 64-127 into bufX ----
        if (ntile < ntiles) pf_hi(ntile * BR);
        CP_COMMIT();

        // ---- epilogue: bias + SiLU + store ----
#pragma unroll
        for (int mt = 0; mt < 2; mt++)
#pragma unroll
            for (int nt = 0; nt < 4; nt++) {
                const int c0 = wn * 32 + nt * 8 + 2 * tig;
                float* C = acc[mt][nt];
#pragma unroll
                for (int h = 0; h < 2; h++) {
                    const int row = rowbase + wm * 32 + mt * 16 + h * 8 + g;
                    if (row < E) {
                        float2 o;
                        o.x = silu_f(C[2 * h + 0] + b2f[c0]);
                        o.y = silu_f(C[2 * h + 1] + b2f[c0 + 1]);
                        *(float2*)(out + (size_t)row * OUTD + c0) = o;
                    }
                }
            }
    }
}

extern "C" void kernel_launch(void* const* d_in, const int* in_sizes, int n_in,
                              void* d_out, int out_size) {
    const float* src = (const float*)d_in[0];
    const float* edg = (const float*)d_in[1];
    const float* W1  = (const float*)d_in[2];
    const float* b1  = (const float*)d_in[3];
    const float* gam = (const float*)d_in[4];
    const float* bet = (const float*)d_in[5];
    const float* W2  = (const float*)d_in[6];
    const float* b2  = (const float*)d_in[7];
    float* out = (float*)d_out;

    const int E = in_sizes[0] / NODE;
    const int ntiles = (E + BR - 1) / BR;

    cudaFuncSetAttribute(edge_mlp_mma,
                         cudaFuncAttributeMaxDynamicSharedMemorySize, SMEM_BYTES);

    int nsm = 148;
    if (cudaDeviceGetAttribute(&nsm, cudaDevAttrMultiProcessorCount, 0) != cudaSuccess
        || nsm <= 0)
        nsm = 148;
    const int grid = nsm < ntiles ? nsm : ntiles;

    edge_mlp_mma<<<grid, THREADS, SMEM_BYTES>>>(src, edg, W1, b1, gam, bet,
                                                W2, b2, out, E, ntiles);
}